// round 14
// baseline (speedup 1.0000x reference)
#include <cuda_runtime.h>
#include <cuda_bf16.h>
#include <cstdint>

// Problem constants (fixed by reference setup_inputs)
#define SEQ   3072
#define DIM   1280
#define NH    16
#define HD    80
#define SEG   1024
#define QKVN  3840
#define SCALE 0.11180339887498948f   // 1/sqrt(80)

// ---------------------------------------------------------------------------
// Scratch (static device globals — allocation-free per harness rules)
// ---------------------------------------------------------------------------
__device__ float g_qkv[SEQ * QKVN];        // qkv = hidden @ qkv_w^T + b

// split-bf16 GEMM operands
__device__ __nv_bfloat16 g_hid_hi [SEQ * DIM],  g_hid_lo [SEQ * DIM];
__device__ __nv_bfloat16 g_qkvw_hi[QKVN * DIM], g_qkvw_lo[QKVN * DIM];
__device__ __nv_bfloat16 g_pw_hi  [DIM * DIM],  g_pw_lo  [DIM * DIM];
__device__ __nv_bfloat16 g_att_hi [SEQ * DIM],  g_att_lo [SEQ * DIM];

// split-bf16 attention operands (Q pre-scaled by 1/sqrt(HD))
__device__ __nv_bfloat16 g_q_hi[NH * SEQ * HD], g_q_lo[NH * SEQ * HD]; // [h][s][d]
__device__ __nv_bfloat16 g_k_hi[NH * SEQ * HD], g_k_lo[NH * SEQ * HD]; // [h][s][d]
__device__ __nv_bfloat16 g_v_hi[NH * HD * SEQ], g_v_lo[NH * HD * SEQ]; // [h][d][s]

__device__ __forceinline__ void split2(float x, __nv_bfloat16& h, __nv_bfloat16& l) {
    h = __float2bfloat16_rn(x);
    l = __float2bfloat16_rn(x - __bfloat162float(h));
}

// 16-byte async copy global -> shared (sm_80 baseline PTX, compute_103-legal)
__device__ __forceinline__ void cp16(char* s, const void* g) {
    uint32_t sa = (uint32_t)__cvta_generic_to_shared(s);
    asm volatile("cp.async.cg.shared.global [%0], [%1], 16;" :: "r"(sa), "l"(g));
}
#define CP_COMMIT()  asm volatile("cp.async.commit_group;" ::: "memory")
#define CP_WAIT(n)   asm volatile("cp.async.wait_group %0;" :: "n"(n) : "memory")

// ldmatrix x4: loads four 8x8 b16 tiles; each lane supplies one row address.
__device__ __forceinline__ void ldsm4(uint32_t* r, const char* p) {
    uint32_t a = (uint32_t)__cvta_generic_to_shared(p);
    asm volatile("ldmatrix.sync.aligned.m8n8.x4.shared.b16 {%0,%1,%2,%3}, [%4];"
        : "=r"(r[0]), "=r"(r[1]), "=r"(r[2]), "=r"(r[3]) : "r"(a));
}

// ---------------------------------------------------------------------------
// fp32 -> (bf16 hi, bf16 lo) split. n must be a multiple of 4.
// ---------------------------------------------------------------------------
__global__ __launch_bounds__(256)
void split_bf16_kernel(const float* __restrict__ src,
                       __nv_bfloat16* __restrict__ hi,
                       __nv_bfloat16* __restrict__ lo, int n4)
{
    int i = blockIdx.x * 256 + threadIdx.x;
    if (i >= n4) return;
    float4 v = ((const float4*)src)[i];
    __nv_bfloat16 h0, h1, h2, h3, l0, l1, l2, l3;
    split2(v.x, h0, l0); split2(v.y, h1, l1);
    split2(v.z, h2, l2); split2(v.w, h3, l3);
    __nv_bfloat162* hp = (__nv_bfloat162*)(hi + 4 * (size_t)i);
    __nv_bfloat162* lp = (__nv_bfloat162*)(lo + 4 * (size_t)i);
    hp[0] = __nv_bfloat162(h0, h1); hp[1] = __nv_bfloat162(h2, h3);
    lp[0] = __nv_bfloat162(l0, l1); lp[1] = __nv_bfloat162(l2, l3);
}

// ---------------------------------------------------------------------------
// Split-bf16 GEMM via mma.sync + ldmatrix, 4-stage cp.async pipeline
// (CUTLASS multistage: ONE __syncthreads per K-chunk, prefetch depth 3).
//   C[m][n] = sum_k A[m][k]*B[n][k] + bias[n]
// Block 128x128, K-chunk 32, 4 x 40KB smem stages, 1 CTA/SM.
// ---------------------------------------------------------------------------
#define MMA_BF16(d, a, b0, b1) \
    asm volatile("mma.sync.aligned.m16n8k16.row.col.f32.bf16.bf16.f32 " \
        "{%0,%1,%2,%3}, {%4,%5,%6,%7}, {%8,%9}, {%0,%1,%2,%3};" \
        : "+f"((d)[0]), "+f"((d)[1]), "+f"((d)[2]), "+f"((d)[3]) \
        : "r"((a)[0]), "r"((a)[1]), "r"((a)[2]), "r"((a)[3]), \
          "r"(b0), "r"(b1))

#define TSTRIDE 80             // bytes per smem row (32 bf16 + 8 pad)
#define TILE_B  (128 * TSTRIDE)
#define GBUF    (4 * TILE_B)   // Ah|Al|Bh|Bl per stage = 40960
#define NSTAGE  4
#define GEMM_SMEM (NSTAGE * GBUF)   // 163840

__device__ __forceinline__ void gemm_issue(
    char* base,
    const __nv_bfloat16* __restrict__ Ah, const __nv_bfloat16* __restrict__ Al,
    const __nv_bfloat16* __restrict__ Bh, const __nv_bfloat16* __restrict__ Bl,
    int bm, int bn, int K, int k0,
    int lrow0, int lrow1, int lkg, int s0, int s1)
{
    const size_t a0 = (size_t)(bm + lrow0) * K + k0 + lkg * 8;
    const size_t a1 = (size_t)(bm + lrow1) * K + k0 + lkg * 8;
    const size_t b0 = (size_t)(bn + lrow0) * K + k0 + lkg * 8;
    const size_t b1 = (size_t)(bn + lrow1) * K + k0 + lkg * 8;
    cp16(base + s0,              Ah + a0);  cp16(base + s1,              Ah + a1);
    cp16(base + TILE_B + s0,     Al + a0);  cp16(base + TILE_B + s1,     Al + a1);
    cp16(base + 2 * TILE_B + s0, Bh + b0);  cp16(base + 2 * TILE_B + s1, Bh + b1);
    cp16(base + 3 * TILE_B + s0, Bl + b0);  cp16(base + 3 * TILE_B + s1, Bl + b1);
    CP_COMMIT();
}

__global__ __launch_bounds__(256)
void mma_gemm_bias(const __nv_bfloat16* __restrict__ Ah,
                   const __nv_bfloat16* __restrict__ Al,
                   const __nv_bfloat16* __restrict__ Bh,
                   const __nv_bfloat16* __restrict__ Bl,
                   const float* __restrict__ bias, float* __restrict__ C,
                   int M, int N, int K)
{
    extern __shared__ __align__(16) char dsm[];

    const int tid  = threadIdx.x;
    const int lane = tid & 31;
    const int wid  = tid >> 5;
    const int wm   = wid & 3;
    const int wn   = wid >> 2;
    const int gr   = lane >> 2;
    const int tg   = lane & 3;
    const int l7   = lane & 7;
    const int lt   = lane >> 3;            // ldmatrix tile index 0..3
    const int rowA = (lt & 1) * 8 + l7;
    const int colA = (lt >> 1) * 16;
    const int rowB = (lt >> 1) * 8 + l7;
    const int colB = (lt & 1) * 16;

    const int bm = blockIdx.y * 128;
    const int bn = blockIdx.x * 128;

    const int lrow0 = tid >> 2, lkg = tid & 3;
    const int lrow1 = lrow0 + 64;
    const int s0 = lrow0 * TSTRIDE + lkg * 16;
    const int s1 = lrow1 * TSTRIDE + lkg * 16;

    float acc[2][8][4];
    #pragma unroll
    for (int mt = 0; mt < 2; ++mt)
        #pragma unroll
        for (int nt = 0; nt < 8; ++nt)
            #pragma unroll
            for (int q = 0; q < 4; ++q) acc[mt][nt][q] = 0.0f;

    // prologue: prefetch stages 0..NSTAGE-2
    #pragma unroll
    for (int s = 0; s < NSTAGE - 1; ++s)
        gemm_issue(dsm + s * GBUF, Ah, Al, Bh, Bl, bm, bn, K, s * 32,
                   lrow0, lrow1, lkg, s0, s1);

    const int nch = K / 32;
    for (int i = 0; i < nch; ++i) {
        CP_WAIT(NSTAGE - 2);   // chunk i's group is complete
        __syncthreads();       // visibility for all threads' copies of stage i
                               // + WAR guard for overwriting stage (i-1)%NSTAGE

        const int nxt = i + NSTAGE - 1;
        if (nxt < nch) {
            gemm_issue(dsm + (nxt % NSTAGE) * GBUF, Ah, Al, Bh, Bl,
                       bm, bn, K, nxt * 32, lrow0, lrow1, lkg, s0, s1);
        } else {
            CP_COMMIT();       // empty group keeps wait accounting uniform
        }

        char* cur = dsm + (i % NSTAGE) * GBUF;
        char* sAh = cur;
        char* sAl = cur + TILE_B;
        char* sBh = cur + 2 * TILE_B;
        char* sBl = cur + 3 * TILE_B;

        #pragma unroll
        for (int ks = 0; ks < 2; ++ks) {
            const int kb = ks * 32;
            uint32_t ah[2][4], al[2][4];
            #pragma unroll
            for (int mt = 0; mt < 2; ++mt) {
                const int ao = (wm * 32 + mt * 16 + rowA) * TSTRIDE + kb + colA;
                ldsm4(ah[mt], sAh + ao);
                ldsm4(al[mt], sAl + ao);
            }
            #pragma unroll
            for (int p = 0; p < 4; ++p) {
                uint32_t bh[4], bl[4];
                const int bo = (wn * 64 + p * 16 + rowB) * TSTRIDE + kb + colB;
                ldsm4(bh, sBh + bo);
                ldsm4(bl, sBl + bo);
                #pragma unroll
                for (int hf = 0; hf < 2; ++hf)
                    #pragma unroll
                    for (int mt = 0; mt < 2; ++mt)
                        MMA_BF16(acc[mt][p * 2 + hf], ah[mt], bh[hf * 2], bh[hf * 2 + 1]);
                #pragma unroll
                for (int hf = 0; hf < 2; ++hf)
                    #pragma unroll
                    for (int mt = 0; mt < 2; ++mt)
                        MMA_BF16(acc[mt][p * 2 + hf], ah[mt], bl[hf * 2], bl[hf * 2 + 1]);
                #pragma unroll
                for (int hf = 0; hf < 2; ++hf)
                    #pragma unroll
                    for (int mt = 0; mt < 2; ++mt)
                        MMA_BF16(acc[mt][p * 2 + hf], al[mt], bh[hf * 2], bh[hf * 2 + 1]);
            }
        }
        // NOTE: no trailing __syncthreads — next iteration's barrier covers WAR
    }

    #pragma unroll
    for (int mt = 0; mt < 2; ++mt) {
        const int row = bm + wm * 32 + mt * 16 + gr;
        #pragma unroll
        for (int nt = 0; nt < 8; ++nt) {
            const int col = bn + wn * 64 + nt * 8 + tg * 2;
            const float b0 = bias[col], b1 = bias[col + 1];
            float2 v0 = make_float2(acc[mt][nt][0] + b0, acc[mt][nt][1] + b1);
            float2 v1 = make_float2(acc[mt][nt][2] + b0, acc[mt][nt][3] + b1);
            *(float2*)(C + (size_t)row * N + col)       = v0;
            *(float2*)(C + (size_t)(row + 8) * N + col) = v1;
        }
    }
}

// ---------------------------------------------------------------------------
// RoPE + split + scatter:
//   qkv[s][3840] -> q_hi/lo [h][s][d] (roped, *SCALE), k_hi/lo [h][s][d],
//                   v_hi/lo [h][d][s]
// ---------------------------------------------------------------------------
__global__ __launch_bounds__(256)
void rope_split_kernel(const float* __restrict__ qkv,
                       const float* __restrict__ cosb,
                       const float* __restrict__ sinb,
                       __nv_bfloat16* __restrict__ qh, __nv_bfloat16* __restrict__ ql,
                       __nv_bfloat16* __restrict__ kh, __nv_bfloat16* __restrict__ kl,
                       __nv_bfloat16* __restrict__ vh, __nv_bfloat16* __restrict__ vl)
{
    __shared__ float qs[64][81];
    __shared__ float ks[64][81];
    const int h  = blockIdx.y;
    const int s0 = blockIdx.x * 64;
    const int tid = threadIdx.x;

    for (int idx = tid; idx < 64 * 80; idx += 256) {
        int s = idx / 80, d = idx - s * 80;
        const float* row = qkv + (size_t)(s0 + s) * QKVN + h * HD + d;
        qs[s][d] = row[0];
        ks[s][d] = row[DIM];
    }
    __syncthreads();

    for (int idx = tid; idx < 64 * 80; idx += 256) {
        int s = idx / 80, d = idx - s * 80;
        float c  = cosb[(size_t)(s0 + s) * HD + d];
        float sn = sinb[(size_t)(s0 + s) * HD + d];
        int d2 = (d < 40) ? d + 40 : d - 40;
        float qv = qs[s][d], kv = ks[s][d];
        float qr = (d < 40) ? -qs[s][d2] : qs[s][d2];
        float kr = (d < 40) ? -ks[s][d2] : ks[s][d2];
        float qo = (qv * c + qr * sn) * SCALE;   // fold 1/sqrt(HD) into Q
        float ko = kv * c + kr * sn;
        size_t o = ((size_t)h * SEQ + s0 + s) * HD + d;
        __nv_bfloat16 hh, ll;
        split2(qo, hh, ll); qh[o] = hh; ql[o] = ll;
        split2(ko, hh, ll); kh[o] = hh; kl[o] = ll;
    }

    // V: stage then transpose to [h][d][s]
    __syncthreads();
    for (int idx = tid; idx < 64 * 80; idx += 256) {
        int s = idx / 80, d = idx - s * 80;
        qs[s][d] = qkv[(size_t)(s0 + s) * QKVN + 2 * DIM + h * HD + d];
    }
    __syncthreads();
    for (int idx = tid; idx < 64 * 80; idx += 256) {
        int d = idx >> 6, s = idx & 63;
        float v = qs[s][d];
        size_t o = ((size_t)(h * HD + d)) * SEQ + s0 + s;
        __nv_bfloat16 hh, ll;
        split2(v, hh, ll); vh[o] = hh; vl[o] = ll;
    }
}

// ---------------------------------------------------------------------------
// Flash attention on the tensor pipe. KV chunk 32, smem 91KB, 2 CTAs/SM.
// (unchanged from R13)
// ---------------------------------------------------------------------------
#define QSTR 176
#define VSTR 80
#define KCH  32
#define KVB  (KCH * QSTR * 2 + 80 * VSTR * 2)       // 24064 per stage
#define QB   (128 * QSTR * 2)                        // 45056
#define ATTN_SMEM (QB + 2 * KVB)                     // 93184

__global__ __launch_bounds__(256, 2)
void flash_mma_kernel(const __nv_bfloat16* __restrict__ qh_g,
                      const __nv_bfloat16* __restrict__ ql_g,
                      const __nv_bfloat16* __restrict__ kh_g,
                      const __nv_bfloat16* __restrict__ kl_g,
                      const __nv_bfloat16* __restrict__ vh_g,
                      const __nv_bfloat16* __restrict__ vl_g,
                      __nv_bfloat16* __restrict__ oh_g,
                      __nv_bfloat16* __restrict__ ol_g)
{
    extern __shared__ __align__(16) char sm[];
    char* sQh = sm;
    char* sQl = sm + 128 * QSTR;

    const int h   = blockIdx.z;
    const int seg = blockIdx.y;
    const int qt  = blockIdx.x;
    const int sbase = seg * SEG;
    const int q0 = sbase + qt * 128;
    const int tid = threadIdx.x;
    const int lane = tid & 31;
    const int wid = tid >> 5;
    const int gr = lane >> 2;
    const int tg = lane & 3;
    const int l7 = lane & 7;
    const int lt = lane >> 3;
    const int rowA = (lt & 1) * 8 + l7;
    const int colA = (lt >> 1) * 16;
    const int rowB = (lt >> 1) * 8 + l7;
    const int colB = (lt & 1) * 16;

    const uint4* k4h = (const uint4*)kh_g + ((size_t)h * SEQ + sbase) * 10;
    const uint4* k4l = (const uint4*)kl_g + ((size_t)h * SEQ + sbase) * 10;
    const uint4* v4h = (const uint4*)vh_g;
    const uint4* v4l = (const uint4*)vl_g;

    // issue K/V chunk n0 (32 rows / 32 cols) into stage buffer b
    auto issue_kv = [&](int n0, int b) {
        char* kb = sm + QB + b * KVB;
        char* kKh = kb;
        char* kKl = kb + KCH * QSTR;
        char* kVh = kb + 2 * KCH * QSTR;
        char* kVl = kb + 2 * KCH * QSTR + 80 * VSTR;
        for (int idx = tid; idx < 320; idx += 256) {
            int r = idx / 10, c = idx - r * 10;     // K: 32 rows x 10 uint4
            cp16(kKh + r * QSTR + c * 16, k4h + (n0 + r) * 10 + c);
            cp16(kKl + r * QSTR + c * 16, k4l + (n0 + r) * 10 + c);
        }
        for (int idx = tid; idx < 320; idx += 256) {
            int d = idx >> 2, c = idx & 3;          // V: 80 rows x 4 uint4
            size_t g = (size_t)(h * HD + d) * (SEQ / 8) + ((sbase + n0) >> 3) + c;
            cp16(kVh + d * VSTR + c * 16, v4h + g);
            cp16(kVl + d * VSTR + c * 16, v4l + g);
        }
        CP_COMMIT();
    };

    // ---- Q tile via cp.async; joins the chunk-0 group ----
    {
        const uint4* q4h = (const uint4*)qh_g + ((size_t)h * SEQ + q0) * 10;
        const uint4* q4l = (const uint4*)ql_g + ((size_t)h * SEQ + q0) * 10;
        for (int idx = tid; idx < 1280; idx += 256) {
            int r = idx / 10, c = idx - r * 10;
            cp16(sQh + r * QSTR + c * 16, q4h + idx);
            cp16(sQl + r * QSTR + c * 16, q4l + idx);
        }
    }
    issue_kv(0, 0);   // commit: Q + chunk0

    float oacc[10][4];
    #pragma unroll
    for (int n = 0; n < 10; ++n)
        #pragma unroll
        for (int q = 0; q < 4; ++q) oacc[n][q] = 0.0f;
    float mi0 = -1e30f, mi1 = -1e30f, li0 = 0.0f, li1 = 0.0f;

    const int qrow = wid * 16;
    const int NCH = SEG / KCH;   // 32

    for (int cix = 0; cix < NCH; ++cix) {
        if (cix + 1 < NCH) {
            issue_kv((cix + 1) * KCH, (cix + 1) & 1);
            CP_WAIT(1);
        } else {
            CP_WAIT(0);
        }
        __syncthreads();

        char* kb  = sm + QB + (cix & 1) * KVB;
        char* sKh = kb;
        char* sKl = kb + KCH * QSTR;
        char* sVh = kb + 2 * KCH * QSTR;
        char* sVl = kb + 2 * KCH * QSTR + 80 * VSTR;

        // ---- S = Q K^T (scale pre-folded into Q): 4 n8 tiles ----
        float sacc[4][4];
        #pragma unroll
        for (int j = 0; j < 4; ++j)
            #pragma unroll
            for (int q = 0; q < 4; ++q) sacc[j][q] = 0.0f;

        #pragma unroll
        for (int ks = 0; ks < 5; ++ks) {
            uint32_t qa_h[4], qa_l[4];
            const int qo = (qrow + rowA) * QSTR + ks * 32 + colA;
            ldsm4(qa_h, sQh + qo);
            ldsm4(qa_l, sQl + qo);
            uint32_t kf_h[2][4], kf_l[2][4];
            #pragma unroll
            for (int p = 0; p < 2; ++p) {
                const int ko = (p * 16 + rowB) * QSTR + ks * 32 + colB;
                ldsm4(kf_h[p], sKh + ko);
                ldsm4(kf_l[p], sKl + ko);
            }
            #pragma unroll
            for (int p = 0; p < 2; ++p)
                #pragma unroll
                for (int hf = 0; hf < 2; ++hf)
                    MMA_BF16(sacc[p * 2 + hf], qa_h, kf_h[p][hf * 2], kf_h[p][hf * 2 + 1]);
            #pragma unroll
            for (int p = 0; p < 2; ++p)
                #pragma unroll
                for (int hf = 0; hf < 2; ++hf)
                    MMA_BF16(sacc[p * 2 + hf], qa_h, kf_l[p][hf * 2], kf_l[p][hf * 2 + 1]);
            #pragma unroll
            for (int p = 0; p < 2; ++p)
                #pragma unroll
                for (int hf = 0; hf < 2; ++hf)
                    MMA_BF16(sacc[p * 2 + hf], qa_l, kf_h[p][hf * 2], kf_h[p][hf * 2 + 1]);
        }

        // ---- online softmax (rows gr and gr+8 of this warp's 16) ----
        float mx0 = -1e30f, mx1 = -1e30f;
        #pragma unroll
        for (int j = 0; j < 4; ++j) {
            mx0 = fmaxf(mx0, fmaxf(sacc[j][0], sacc[j][1]));
            mx1 = fmaxf(mx1, fmaxf(sacc[j][2], sacc[j][3]));
        }
        mx0 = fmaxf(mx0, __shfl_xor_sync(0xffffffffu, mx0, 1));
        mx0 = fmaxf(mx0, __shfl_xor_sync(0xffffffffu, mx0, 2));
        mx1 = fmaxf(mx1, __shfl_xor_sync(0xffffffffu, mx1, 1));
        mx1 = fmaxf(mx1, __shfl_xor_sync(0xffffffffu, mx1, 2));

        const float mn0 = fmaxf(mi0, mx0);
        const float mn1 = fmaxf(mi1, mx1);
        const float al0 = __expf(mi0 - mn0);
        const float al1 = __expf(mi1 - mn1);
        mi0 = mn0; mi1 = mn1;

        float ps0 = 0.0f, ps1 = 0.0f;
        uint32_t pph[4][2], ppl[4][2];
        #pragma unroll
        for (int j = 0; j < 4; ++j) {
            float p0 = __expf(sacc[j][0] - mn0);
            float p1 = __expf(sacc[j][1] - mn0);
            float p2 = __expf(sacc[j][2] - mn1);
            float p3 = __expf(sacc[j][3] - mn1);
            ps0 += p0 + p1; ps1 += p2 + p3;
            __nv_bfloat16 h0, h1, h2, h3, l0, l1, l2, l3;
            split2(p0, h0, l0); split2(p1, h1, l1);
            split2(p2, h2, l2); split2(p3, h3, l3);
            pph[j][0] = ((uint32_t)__bfloat16_as_ushort(h1) << 16) | __bfloat16_as_ushort(h0);
            pph[j][1] = ((uint32_t)__bfloat16_as_ushort(h3) << 16) | __bfloat16_as_ushort(h2);
            ppl[j][0] = ((uint32_t)__bfloat16_as_ushort(l1) << 16) | __bfloat16_as_ushort(l0);
            ppl[j][1] = ((uint32_t)__bfloat16_as_ushort(l3) << 16) | __bfloat16_as_ushort(l2);
        }
        ps0 += __shfl_xor_sync(0xffffffffu, ps0, 1);
        ps0 += __shfl_xor_sync(0xffffffffu, ps0, 2);
        ps1 += __shfl_xor_sync(0xffffffffu, ps1, 1);
        ps1 += __shfl_xor_sync(0xffffffffu, ps1, 2);
        li0 = li0 * al0 + ps0;
        li1 = li1 * al1 + ps1;

        #pragma unroll
        for (int n = 0; n < 10; ++n) {
            oacc[n][0] *= al0; oacc[n][1] *= al0;
            oacc[n][2] *= al1; oacc[n][3] *= al1;
        }

        // ---- O += P V (P already in A-fragment layout); 2 k16 steps ----
        #pragma unroll
        for (int t = 0; t < 2; ++t) {
            uint32_t pa_h[4] = {pph[2*t][0], pph[2*t][1], pph[2*t+1][0], pph[2*t+1][1]};
            uint32_t pa_l[4] = {ppl[2*t][0], ppl[2*t][1], ppl[2*t+1][0], ppl[2*t+1][1]};
            #pragma unroll
            for (int p = 0; p < 5; ++p) {
                uint32_t vf_h[4], vf_l[4];
                const int vo = (p * 16 + rowB) * VSTR + t * 32 + colB;
                ldsm4(vf_h, sVh + vo);
                ldsm4(vf_l, sVl + vo);
                #pragma unroll
                for (int hf = 0; hf < 2; ++hf)
                    MMA_BF16(oacc[p * 2 + hf], pa_h, vf_h[hf * 2], vf_h[hf * 2 + 1]);
                #pragma unroll
                for (int hf = 0; hf < 2; ++hf)
                    MMA_BF16(oacc[p * 2 + hf], pa_h, vf_l[hf * 2], vf_l[hf * 2 + 1]);
                #pragma unroll
                for (int hf = 0; hf < 2; ++hf)
                    MMA_BF16(oacc[p * 2 + hf], pa_l, vf_h[hf * 2], vf_h[hf * 2 + 1]);
            }
        }
        __syncthreads();   // all warps done with this stage before it is refilled
    }

    // ---- epilogue: normalize, split to bf16 hi/lo, write [s][h*HD+d] ----
    const float inv0 = 1.0f / li0;
    const float inv1 = 1.0f / li1;
    const int r0 = q0 + qrow + gr;
    const int r1 = r0 + 8;
    #pragma unroll
    for (int n = 0; n < 10; ++n) {
        const int col = h * HD + n * 8 + tg * 2;
        float f0 = oacc[n][0] * inv0, f1 = oacc[n][1] * inv0;
        float f2 = oacc[n][2] * inv1, f3 = oacc[n][3] * inv1;
        __nv_bfloat16 h0, h1, h2, h3, l0, l1, l2, l3;
        split2(f0, h0, l0); split2(f1, h1, l1);
        split2(f2, h2, l2); split2(f3, h3, l3);
        *(__nv_bfloat162*)(oh_g + (size_t)r0 * DIM + col) = __nv_bfloat162(h0, h1);
        *(__nv_bfloat162*)(ol_g + (size_t)r0 * DIM + col) = __nv_bfloat162(l0, l1);
        *(__nv_bfloat162*)(oh_g + (size_t)r1 * DIM + col) = __nv_bfloat162(h2, h3);
        *(__nv_bfloat162*)(ol_g + (size_t)r1 * DIM + col) = __nv_bfloat162(l2, l3);
    }
}

// ---------------------------------------------------------------------------
// kernel_launch
// ---------------------------------------------------------------------------
extern "C" void kernel_launch(void* const* d_in, const int* in_sizes, int n_in,
                              void* d_out, int out_size)
{
    const float* hidden = (const float*)d_in[0];
    const float* cosb   = (const float*)d_in[1];
    const float* sinb   = (const float*)d_in[2];
    const float* qkv_w  = (const float*)d_in[3];
    const float* qkv_b  = (const float*)d_in[4];
    const float* proj_w = (const float*)d_in[5];
    const float* proj_b = (const float*)d_in[6];
    float* out = (float*)d_out;

    float* qkv;
    cudaGetSymbolAddress((void**)&qkv, g_qkv);

    __nv_bfloat16 *hid_h, *hid_l, *qw_h, *qw_l, *pw_h, *pw_l, *at_h, *at_l;
    __nv_bfloat16 *q_h, *q_l, *k_h, *k_l, *v_h, *v_l;
    cudaGetSymbolAddress((void**)&hid_h, g_hid_hi);
    cudaGetSymbolAddress((void**)&hid_l, g_hid_lo);
    cudaGetSymbolAddress((void**)&qw_h,  g_qkvw_hi);
    cudaGetSymbolAddress((void**)&qw_l,  g_qkvw_lo);
    cudaGetSymbolAddress((void**)&pw_h,  g_pw_hi);
    cudaGetSymbolAddress((void**)&pw_l,  g_pw_lo);
    cudaGetSymbolAddress((void**)&at_h,  g_att_hi);
    cudaGetSymbolAddress((void**)&at_l,  g_att_lo);
    cudaGetSymbolAddress((void**)&q_h,   g_q_hi);
    cudaGetSymbolAddress((void**)&q_l,   g_q_lo);
    cudaGetSymbolAddress((void**)&k_h,   g_k_hi);
    cudaGetSymbolAddress((void**)&k_l,   g_k_lo);
    cudaGetSymbolAddress((void**)&v_h,   g_v_hi);
    cudaGetSymbolAddress((void**)&v_l,   g_v_lo);

    cudaFuncSetAttribute(mma_gemm_bias,
                         cudaFuncAttributeMaxDynamicSharedMemorySize, GEMM_SMEM);
    cudaFuncSetAttribute(flash_mma_kernel,
                         cudaFuncAttributeMaxDynamicSharedMemorySize, ATTN_SMEM);

    // 0) split fp32 inputs into bf16 hi/lo
    {
        int n4 = SEQ * DIM / 4;
        split_bf16_kernel<<<(n4 + 255) / 256, 256>>>(hidden, hid_h, hid_l, n4);
        n4 = QKVN * DIM / 4;
        split_bf16_kernel<<<(n4 + 255) / 256, 256>>>(qkv_w, qw_h, qw_l, n4);
        n4 = DIM * DIM / 4;
        split_bf16_kernel<<<(n4 + 255) / 256, 256>>>(proj_w, pw_h, pw_l, n4);
    }

    // 1) QKV GEMM + bias (4-stage multistage pipeline, 1 barrier/chunk)
    mma_gemm_bias<<<dim3(QKVN / 128, SEQ / 128), 256, GEMM_SMEM>>>(
        hid_h, hid_l, qw_h, qw_l, qkv_b, qkv, SEQ, QKVN, DIM);

    // 2) RoPE + split + scatter to attention layouts
    rope_split_kernel<<<dim3(SEQ / 64, NH), 256>>>(
        qkv, cosb, sinb, q_h, q_l, k_h, k_l, v_h, v_l);

    // 3) Block-diagonal flash attention (2 CTAs/SM, KV chunk 32)
    flash_mma_kernel<<<dim3(SEG / 128, 3, NH), 256, ATTN_SMEM>>>(
        q_h, q_l, k_h, k_l, v_h, v_l, at_h, at_l);

    // 4) Proj GEMM + bias
    mma_gemm_bias<<<dim3(DIM / 128, SEQ / 128), 256, GEMM_SMEM>>>(
        at_h, at_l, pw_h, pw_l, proj_b, out, SEQ, DIM, DIM);
}

// round 15
// speedup vs baseline: 1.1170x; 1.1170x over previous
#include <cuda_runtime.h>
#include <cuda_bf16.h>
#include <cstdint>

// Problem constants (fixed by reference setup_inputs)
#define SEQ   3072
#define DIM   1280
#define NH    16
#define HD    80
#define SEG   1024
#define QKVN  3840
#define SCALE 0.11180339887498948f   // 1/sqrt(80)

// ---------------------------------------------------------------------------
// Scratch (static device globals — allocation-free per harness rules)
// ---------------------------------------------------------------------------
__device__ float g_qkv[SEQ * QKVN];        // qkv = hidden @ qkv_w^T + b

// split-bf16 GEMM operands
__device__ __nv_bfloat16 g_hid_hi [SEQ * DIM],  g_hid_lo [SEQ * DIM];
__device__ __nv_bfloat16 g_qkvw_hi[QKVN * DIM], g_qkvw_lo[QKVN * DIM];
__device__ __nv_bfloat16 g_pw_hi  [DIM * DIM],  g_pw_lo  [DIM * DIM];
__device__ __nv_bfloat16 g_att_hi [SEQ * DIM],  g_att_lo [SEQ * DIM];

// split-bf16 attention operands (Q pre-scaled by 1/sqrt(HD))
__device__ __nv_bfloat16 g_q_hi[NH * SEQ * HD], g_q_lo[NH * SEQ * HD]; // [h][s][d]
__device__ __nv_bfloat16 g_k_hi[NH * SEQ * HD], g_k_lo[NH * SEQ * HD]; // [h][s][d]
__device__ __nv_bfloat16 g_v_hi[NH * HD * SEQ], g_v_lo[NH * HD * SEQ]; // [h][d][s]

__device__ __forceinline__ void split2(float x, __nv_bfloat16& h, __nv_bfloat16& l) {
    h = __float2bfloat16_rn(x);
    l = __float2bfloat16_rn(x - __bfloat162float(h));
}

// 16-byte async copy global -> shared (sm_80 baseline PTX, compute_103-legal)
__device__ __forceinline__ void cp16(char* s, const void* g) {
    uint32_t sa = (uint32_t)__cvta_generic_to_shared(s);
    asm volatile("cp.async.cg.shared.global [%0], [%1], 16;" :: "r"(sa), "l"(g));
}
#define CP_COMMIT()  asm volatile("cp.async.commit_group;" ::: "memory")
#define CP_WAIT(n)   asm volatile("cp.async.wait_group %0;" :: "n"(n) : "memory")

// ldmatrix x4: loads four 8x8 b16 tiles; each lane supplies one row address.
__device__ __forceinline__ void ldsm4(uint32_t* r, const char* p) {
    uint32_t a = (uint32_t)__cvta_generic_to_shared(p);
    asm volatile("ldmatrix.sync.aligned.m8n8.x4.shared.b16 {%0,%1,%2,%3}, [%4];"
        : "=r"(r[0]), "=r"(r[1]), "=r"(r[2]), "=r"(r[3]) : "r"(a));
}

// ---------------------------------------------------------------------------
// fp32 -> (bf16 hi, bf16 lo) split. n must be a multiple of 4.
// ---------------------------------------------------------------------------
__global__ __launch_bounds__(256)
void split_bf16_kernel(const float* __restrict__ src,
                       __nv_bfloat16* __restrict__ hi,
                       __nv_bfloat16* __restrict__ lo, int n4)
{
    int i = blockIdx.x * 256 + threadIdx.x;
    if (i >= n4) return;
    float4 v = ((const float4*)src)[i];
    __nv_bfloat16 h0, h1, h2, h3, l0, l1, l2, l3;
    split2(v.x, h0, l0); split2(v.y, h1, l1);
    split2(v.z, h2, l2); split2(v.w, h3, l3);
    __nv_bfloat162* hp = (__nv_bfloat162*)(hi + 4 * (size_t)i);
    __nv_bfloat162* lp = (__nv_bfloat162*)(lo + 4 * (size_t)i);
    hp[0] = __nv_bfloat162(h0, h1); hp[1] = __nv_bfloat162(h2, h3);
    lp[0] = __nv_bfloat162(l0, l1); lp[1] = __nv_bfloat162(l2, l3);
}

// ---------------------------------------------------------------------------
// Split-bf16 GEMM via mma.sync + ldmatrix. 2-stage cp.async pipeline,
// 2 CTAs/SM, ONE __syncthreads per K-chunk (wait -> sync -> issue -> compute;
// the barrier also covers WAR on the buffer being refilled, whose readers
// finished one iteration earlier).
// ---------------------------------------------------------------------------
#define MMA_BF16(d, a, b0, b1) \
    asm volatile("mma.sync.aligned.m16n8k16.row.col.f32.bf16.bf16.f32 " \
        "{%0,%1,%2,%3}, {%4,%5,%6,%7}, {%8,%9}, {%0,%1,%2,%3};" \
        : "+f"((d)[0]), "+f"((d)[1]), "+f"((d)[2]), "+f"((d)[3]) \
        : "r"((a)[0]), "r"((a)[1]), "r"((a)[2]), "r"((a)[3]), \
          "r"(b0), "r"(b1))

#define TSTRIDE 80             // bytes per smem row (32 bf16 + 8 pad)
#define TILE_B  (128 * TSTRIDE)
#define GBUF    (4 * TILE_B)   // Ah|Al|Bh|Bl per stage = 40960
#define GEMM_SMEM (2 * GBUF)   // 81920

__device__ __forceinline__ void gemm_issue(
    char* base,
    const __nv_bfloat16* __restrict__ Ah, const __nv_bfloat16* __restrict__ Al,
    const __nv_bfloat16* __restrict__ Bh, const __nv_bfloat16* __restrict__ Bl,
    int bm, int bn, int K, int k0,
    int lrow0, int lrow1, int lkg, int s0, int s1)
{
    const size_t a0 = (size_t)(bm + lrow0) * K + k0 + lkg * 8;
    const size_t a1 = (size_t)(bm + lrow1) * K + k0 + lkg * 8;
    const size_t b0 = (size_t)(bn + lrow0) * K + k0 + lkg * 8;
    const size_t b1 = (size_t)(bn + lrow1) * K + k0 + lkg * 8;
    cp16(base + s0,              Ah + a0);  cp16(base + s1,              Ah + a1);
    cp16(base + TILE_B + s0,     Al + a0);  cp16(base + TILE_B + s1,     Al + a1);
    cp16(base + 2 * TILE_B + s0, Bh + b0);  cp16(base + 2 * TILE_B + s1, Bh + b1);
    cp16(base + 3 * TILE_B + s0, Bl + b0);  cp16(base + 3 * TILE_B + s1, Bl + b1);
    CP_COMMIT();
}

__global__ __launch_bounds__(256, 2)
void mma_gemm_bias(const __nv_bfloat16* __restrict__ Ah,
                   const __nv_bfloat16* __restrict__ Al,
                   const __nv_bfloat16* __restrict__ Bh,
                   const __nv_bfloat16* __restrict__ Bl,
                   const float* __restrict__ bias, float* __restrict__ C,
                   int M, int N, int K)
{
    extern __shared__ __align__(16) char dsm[];

    const int tid  = threadIdx.x;
    const int lane = tid & 31;
    const int wid  = tid >> 5;
    const int wm   = wid & 3;
    const int wn   = wid >> 2;
    const int gr   = lane >> 2;
    const int tg   = lane & 3;
    const int l7   = lane & 7;
    const int lt   = lane >> 3;            // ldmatrix tile index 0..3
    const int rowA = (lt & 1) * 8 + l7;
    const int colA = (lt >> 1) * 16;
    const int rowB = (lt >> 1) * 8 + l7;
    const int colB = (lt & 1) * 16;

    const int bm = blockIdx.y * 128;
    const int bn = blockIdx.x * 128;

    const int lrow0 = tid >> 2, lkg = tid & 3;
    const int lrow1 = lrow0 + 64;
    const int s0 = lrow0 * TSTRIDE + lkg * 16;
    const int s1 = lrow1 * TSTRIDE + lkg * 16;

    float acc[2][8][4];
    #pragma unroll
    for (int mt = 0; mt < 2; ++mt)
        #pragma unroll
        for (int nt = 0; nt < 8; ++nt)
            #pragma unroll
            for (int q = 0; q < 4; ++q) acc[mt][nt][q] = 0.0f;

    // prologue: issue chunk 0 into stage 0
    gemm_issue(dsm, Ah, Al, Bh, Bl, bm, bn, K, 0, lrow0, lrow1, lkg, s0, s1);

    const int nch = K / 32;
    for (int i = 0; i < nch; ++i) {
        CP_WAIT(0);            // chunk i complete (only group in flight)
        __syncthreads();       // data visible to all + WAR guard for refill

        if (i + 1 < nch)       // refill the other stage while computing
            gemm_issue(dsm + ((i + 1) & 1) * GBUF, Ah, Al, Bh, Bl,
                       bm, bn, K, (i + 1) * 32, lrow0, lrow1, lkg, s0, s1);

        char* cur = dsm + (i & 1) * GBUF;
        char* sAh = cur;
        char* sAl = cur + TILE_B;
        char* sBh = cur + 2 * TILE_B;
        char* sBl = cur + 3 * TILE_B;

        #pragma unroll
        for (int ks = 0; ks < 2; ++ks) {
            const int kb = ks * 32;
            uint32_t ah[2][4], al[2][4];
            #pragma unroll
            for (int mt = 0; mt < 2; ++mt) {
                const int ao = (wm * 32 + mt * 16 + rowA) * TSTRIDE + kb + colA;
                ldsm4(ah[mt], sAh + ao);
                ldsm4(al[mt], sAl + ao);
            }
            #pragma unroll
            for (int p = 0; p < 4; ++p) {
                uint32_t bh[4], bl[4];
                const int bo = (wn * 64 + p * 16 + rowB) * TSTRIDE + kb + colB;
                ldsm4(bh, sBh + bo);
                ldsm4(bl, sBl + bo);
                #pragma unroll
                for (int hf = 0; hf < 2; ++hf)
                    #pragma unroll
                    for (int mt = 0; mt < 2; ++mt)
                        MMA_BF16(acc[mt][p * 2 + hf], ah[mt], bh[hf * 2], bh[hf * 2 + 1]);
                #pragma unroll
                for (int hf = 0; hf < 2; ++hf)
                    #pragma unroll
                    for (int mt = 0; mt < 2; ++mt)
                        MMA_BF16(acc[mt][p * 2 + hf], ah[mt], bl[hf * 2], bl[hf * 2 + 1]);
                #pragma unroll
                for (int hf = 0; hf < 2; ++hf)
                    #pragma unroll
                    for (int mt = 0; mt < 2; ++mt)
                        MMA_BF16(acc[mt][p * 2 + hf], al[mt], bh[hf * 2], bh[hf * 2 + 1]);
            }
        }
        // no trailing barrier: next iteration's single barrier covers WAR
    }

    #pragma unroll
    for (int mt = 0; mt < 2; ++mt) {
        const int row = bm + wm * 32 + mt * 16 + gr;
        #pragma unroll
        for (int nt = 0; nt < 8; ++nt) {
            const int col = bn + wn * 64 + nt * 8 + tg * 2;
            const float b0 = bias[col], b1 = bias[col + 1];
            float2 v0 = make_float2(acc[mt][nt][0] + b0, acc[mt][nt][1] + b1);
            float2 v1 = make_float2(acc[mt][nt][2] + b0, acc[mt][nt][3] + b1);
            *(float2*)(C + (size_t)row * N + col)       = v0;
            *(float2*)(C + (size_t)(row + 8) * N + col) = v1;
        }
    }
}

// ---------------------------------------------------------------------------
// RoPE + split + scatter:
//   qkv[s][3840] -> q_hi/lo [h][s][d] (roped, *SCALE), k_hi/lo [h][s][d],
//                   v_hi/lo [h][d][s]
// ---------------------------------------------------------------------------
__global__ __launch_bounds__(256)
void rope_split_kernel(const float* __restrict__ qkv,
                       const float* __restrict__ cosb,
                       const float* __restrict__ sinb,
                       __nv_bfloat16* __restrict__ qh, __nv_bfloat16* __restrict__ ql,
                       __nv_bfloat16* __restrict__ kh, __nv_bfloat16* __restrict__ kl,
                       __nv_bfloat16* __restrict__ vh, __nv_bfloat16* __restrict__ vl)
{
    __shared__ float qs[64][81];
    __shared__ float ks[64][81];
    const int h  = blockIdx.y;
    const int s0 = blockIdx.x * 64;
    const int tid = threadIdx.x;

    for (int idx = tid; idx < 64 * 80; idx += 256) {
        int s = idx / 80, d = idx - s * 80;
        const float* row = qkv + (size_t)(s0 + s) * QKVN + h * HD + d;
        qs[s][d] = row[0];
        ks[s][d] = row[DIM];
    }
    __syncthreads();

    for (int idx = tid; idx < 64 * 80; idx += 256) {
        int s = idx / 80, d = idx - s * 80;
        float c  = cosb[(size_t)(s0 + s) * HD + d];
        float sn = sinb[(size_t)(s0 + s) * HD + d];
        int d2 = (d < 40) ? d + 40 : d - 40;
        float qv = qs[s][d], kv = ks[s][d];
        float qr = (d < 40) ? -qs[s][d2] : qs[s][d2];
        float kr = (d < 40) ? -ks[s][d2] : ks[s][d2];
        float qo = (qv * c + qr * sn) * SCALE;   // fold 1/sqrt(HD) into Q
        float ko = kv * c + kr * sn;
        size_t o = ((size_t)h * SEQ + s0 + s) * HD + d;
        __nv_bfloat16 hh, ll;
        split2(qo, hh, ll); qh[o] = hh; ql[o] = ll;
        split2(ko, hh, ll); kh[o] = hh; kl[o] = ll;
    }

    // V: stage then transpose to [h][d][s]
    __syncthreads();
    for (int idx = tid; idx < 64 * 80; idx += 256) {
        int s = idx / 80, d = idx - s * 80;
        qs[s][d] = qkv[(size_t)(s0 + s) * QKVN + 2 * DIM + h * HD + d];
    }
    __syncthreads();
    for (int idx = tid; idx < 64 * 80; idx += 256) {
        int d = idx >> 6, s = idx & 63;
        float v = qs[s][d];
        size_t o = ((size_t)(h * HD + d)) * SEQ + s0 + s;
        __nv_bfloat16 hh, ll;
        split2(v, hh, ll); vh[o] = hh; vl[o] = ll;
    }
}

// ---------------------------------------------------------------------------
// Flash attention on the tensor pipe. KV chunk 32, smem 91KB, 2 CTAs/SM,
// ONE __syncthreads per chunk (wait -> sync -> issue -> compute).
// ---------------------------------------------------------------------------
#define QSTR 176
#define VSTR 80
#define KCH  32
#define KVB  (KCH * QSTR * 2 + 80 * VSTR * 2)       // 24064 per stage
#define QB   (128 * QSTR * 2)                        // 45056
#define ATTN_SMEM (QB + 2 * KVB)                     // 93184

__global__ __launch_bounds__(256, 2)
void flash_mma_kernel(const __nv_bfloat16* __restrict__ qh_g,
                      const __nv_bfloat16* __restrict__ ql_g,
                      const __nv_bfloat16* __restrict__ kh_g,
                      const __nv_bfloat16* __restrict__ kl_g,
                      const __nv_bfloat16* __restrict__ vh_g,
                      const __nv_bfloat16* __restrict__ vl_g,
                      __nv_bfloat16* __restrict__ oh_g,
                      __nv_bfloat16* __restrict__ ol_g)
{
    extern __shared__ __align__(16) char sm[];
    char* sQh = sm;
    char* sQl = sm + 128 * QSTR;

    const int h   = blockIdx.z;
    const int seg = blockIdx.y;
    const int qt  = blockIdx.x;
    const int sbase = seg * SEG;
    const int q0 = sbase + qt * 128;
    const int tid = threadIdx.x;
    const int lane = tid & 31;
    const int wid = tid >> 5;
    const int gr = lane >> 2;
    const int tg = lane & 3;
    const int l7 = lane & 7;
    const int lt = lane >> 3;
    const int rowA = (lt & 1) * 8 + l7;
    const int colA = (lt >> 1) * 16;
    const int rowB = (lt >> 1) * 8 + l7;
    const int colB = (lt & 1) * 16;

    const uint4* k4h = (const uint4*)kh_g + ((size_t)h * SEQ + sbase) * 10;
    const uint4* k4l = (const uint4*)kl_g + ((size_t)h * SEQ + sbase) * 10;
    const uint4* v4h = (const uint4*)vh_g;
    const uint4* v4l = (const uint4*)vl_g;

    // issue K/V chunk n0 (32 rows / 32 cols) into stage buffer b
    auto issue_kv = [&](int n0, int b) {
        char* kb = sm + QB + b * KVB;
        char* kKh = kb;
        char* kKl = kb + KCH * QSTR;
        char* kVh = kb + 2 * KCH * QSTR;
        char* kVl = kb + 2 * KCH * QSTR + 80 * VSTR;
        for (int idx = tid; idx < 320; idx += 256) {
            int r = idx / 10, c = idx - r * 10;     // K: 32 rows x 10 uint4
            cp16(kKh + r * QSTR + c * 16, k4h + (n0 + r) * 10 + c);
            cp16(kKl + r * QSTR + c * 16, k4l + (n0 + r) * 10 + c);
        }
        for (int idx = tid; idx < 320; idx += 256) {
            int d = idx >> 2, c = idx & 3;          // V: 80 rows x 4 uint4
            size_t g = (size_t)(h * HD + d) * (SEQ / 8) + ((sbase + n0) >> 3) + c;
            cp16(kVh + d * VSTR + c * 16, v4h + g);
            cp16(kVl + d * VSTR + c * 16, v4l + g);
        }
        CP_COMMIT();
    };

    // ---- Q tile via cp.async; joins the chunk-0 group ----
    {
        const uint4* q4h = (const uint4*)qh_g + ((size_t)h * SEQ + q0) * 10;
        const uint4* q4l = (const uint4*)ql_g + ((size_t)h * SEQ + q0) * 10;
        for (int idx = tid; idx < 1280; idx += 256) {
            int r = idx / 10, c = idx - r * 10;
            cp16(sQh + r * QSTR + c * 16, q4h + idx);
            cp16(sQl + r * QSTR + c * 16, q4l + idx);
        }
    }
    issue_kv(0, 0);   // commit: Q + chunk0

    float oacc[10][4];
    #pragma unroll
    for (int n = 0; n < 10; ++n)
        #pragma unroll
        for (int q = 0; q < 4; ++q) oacc[n][q] = 0.0f;
    float mi0 = -1e30f, mi1 = -1e30f, li0 = 0.0f, li1 = 0.0f;

    const int qrow = wid * 16;
    const int NCH = SEG / KCH;   // 32

    for (int cix = 0; cix < NCH; ++cix) {
        CP_WAIT(0);            // chunk cix (and Q on cix==0) complete
        __syncthreads();       // visibility + WAR guard for refill below

        if (cix + 1 < NCH)
            issue_kv((cix + 1) * KCH, (cix + 1) & 1);

        char* kb  = sm + QB + (cix & 1) * KVB;
        char* sKh = kb;
        char* sKl = kb + KCH * QSTR;
        char* sVh = kb + 2 * KCH * QSTR;
        char* sVl = kb + 2 * KCH * QSTR + 80 * VSTR;

        // ---- S = Q K^T (scale pre-folded into Q): 4 n8 tiles ----
        float sacc[4][4];
        #pragma unroll
        for (int j = 0; j < 4; ++j)
            #pragma unroll
            for (int q = 0; q < 4; ++q) sacc[j][q] = 0.0f;

        #pragma unroll
        for (int ks = 0; ks < 5; ++ks) {
            uint32_t qa_h[4], qa_l[4];
            const int qo = (qrow + rowA) * QSTR + ks * 32 + colA;
            ldsm4(qa_h, sQh + qo);
            ldsm4(qa_l, sQl + qo);
            uint32_t kf_h[2][4], kf_l[2][4];
            #pragma unroll
            for (int p = 0; p < 2; ++p) {
                const int ko = (p * 16 + rowB) * QSTR + ks * 32 + colB;
                ldsm4(kf_h[p], sKh + ko);
                ldsm4(kf_l[p], sKl + ko);
            }
            #pragma unroll
            for (int p = 0; p < 2; ++p)
                #pragma unroll
                for (int hf = 0; hf < 2; ++hf)
                    MMA_BF16(sacc[p * 2 + hf], qa_h, kf_h[p][hf * 2], kf_h[p][hf * 2 + 1]);
            #pragma unroll
            for (int p = 0; p < 2; ++p)
                #pragma unroll
                for (int hf = 0; hf < 2; ++hf)
                    MMA_BF16(sacc[p * 2 + hf], qa_h, kf_l[p][hf * 2], kf_l[p][hf * 2 + 1]);
            #pragma unroll
            for (int p = 0; p < 2; ++p)
                #pragma unroll
                for (int hf = 0; hf < 2; ++hf)
                    MMA_BF16(sacc[p * 2 + hf], qa_l, kf_h[p][hf * 2], kf_h[p][hf * 2 + 1]);
        }

        // ---- online softmax (rows gr and gr+8 of this warp's 16) ----
        float mx0 = -1e30f, mx1 = -1e30f;
        #pragma unroll
        for (int j = 0; j < 4; ++j) {
            mx0 = fmaxf(mx0, fmaxf(sacc[j][0], sacc[j][1]));
            mx1 = fmaxf(mx1, fmaxf(sacc[j][2], sacc[j][3]));
        }
        mx0 = fmaxf(mx0, __shfl_xor_sync(0xffffffffu, mx0, 1));
        mx0 = fmaxf(mx0, __shfl_xor_sync(0xffffffffu, mx0, 2));
        mx1 = fmaxf(mx1, __shfl_xor_sync(0xffffffffu, mx1, 1));
        mx1 = fmaxf(mx1, __shfl_xor_sync(0xffffffffu, mx1, 2));

        const float mn0 = fmaxf(mi0, mx0);
        const float mn1 = fmaxf(mi1, mx1);
        const float al0 = __expf(mi0 - mn0);
        const float al1 = __expf(mi1 - mn1);
        mi0 = mn0; mi1 = mn1;

        float ps0 = 0.0f, ps1 = 0.0f;
        uint32_t pph[4][2], ppl[4][2];
        #pragma unroll
        for (int j = 0; j < 4; ++j) {
            float p0 = __expf(sacc[j][0] - mn0);
            float p1 = __expf(sacc[j][1] - mn0);
            float p2 = __expf(sacc[j][2] - mn1);
            float p3 = __expf(sacc[j][3] - mn1);
            ps0 += p0 + p1; ps1 += p2 + p3;
            __nv_bfloat16 h0, h1, h2, h3, l0, l1, l2, l3;
            split2(p0, h0, l0); split2(p1, h1, l1);
            split2(p2, h2, l2); split2(p3, h3, l3);
            pph[j][0] = ((uint32_t)__bfloat16_as_ushort(h1) << 16) | __bfloat16_as_ushort(h0);
            pph[j][1] = ((uint32_t)__bfloat16_as_ushort(h3) << 16) | __bfloat16_as_ushort(h2);
            ppl[j][0] = ((uint32_t)__bfloat16_as_ushort(l1) << 16) | __bfloat16_as_ushort(l0);
            ppl[j][1] = ((uint32_t)__bfloat16_as_ushort(l3) << 16) | __bfloat16_as_ushort(l2);
        }
        ps0 += __shfl_xor_sync(0xffffffffu, ps0, 1);
        ps0 += __shfl_xor_sync(0xffffffffu, ps0, 2);
        ps1 += __shfl_xor_sync(0xffffffffu, ps1, 1);
        ps1 += __shfl_xor_sync(0xffffffffu, ps1, 2);
        li0 = li0 * al0 + ps0;
        li1 = li1 * al1 + ps1;

        #pragma unroll
        for (int n = 0; n < 10; ++n) {
            oacc[n][0] *= al0; oacc[n][1] *= al0;
            oacc[n][2] *= al1; oacc[n][3] *= al1;
        }

        // ---- O += P V (P already in A-fragment layout); 2 k16 steps ----
        #pragma unroll
        for (int t = 0; t < 2; ++t) {
            uint32_t pa_h[4] = {pph[2*t][0], pph[2*t][1], pph[2*t+1][0], pph[2*t+1][1]};
            uint32_t pa_l[4] = {ppl[2*t][0], ppl[2*t][1], ppl[2*t+1][0], ppl[2*t+1][1]};
            #pragma unroll
            for (int p = 0; p < 5; ++p) {
                uint32_t vf_h[4], vf_l[4];
                const int vo = (p * 16 + rowB) * VSTR + t * 32 + colB;
                ldsm4(vf_h, sVh + vo);
                ldsm4(vf_l, sVl + vo);
                #pragma unroll
                for (int hf = 0; hf < 2; ++hf)
                    MMA_BF16(oacc[p * 2 + hf], pa_h, vf_h[hf * 2], vf_h[hf * 2 + 1]);
                #pragma unroll
                for (int hf = 0; hf < 2; ++hf)
                    MMA_BF16(oacc[p * 2 + hf], pa_h, vf_l[hf * 2], vf_l[hf * 2 + 1]);
                #pragma unroll
                for (int hf = 0; hf < 2; ++hf)
                    MMA_BF16(oacc[p * 2 + hf], pa_l, vf_h[hf * 2], vf_h[hf * 2 + 1]);
            }
        }
        // no trailing barrier: next iteration's single barrier covers WAR
    }

    // ---- epilogue: normalize, split to bf16 hi/lo, write [s][h*HD+d] ----
    const float inv0 = 1.0f / li0;
    const float inv1 = 1.0f / li1;
    const int r0 = q0 + qrow + gr;
    const int r1 = r0 + 8;
    #pragma unroll
    for (int n = 0; n < 10; ++n) {
        const int col = h * HD + n * 8 + tg * 2;
        float f0 = oacc[n][0] * inv0, f1 = oacc[n][1] * inv0;
        float f2 = oacc[n][2] * inv1, f3 = oacc[n][3] * inv1;
        __nv_bfloat16 h0, h1, h2, h3, l0, l1, l2, l3;
        split2(f0, h0, l0); split2(f1, h1, l1);
        split2(f2, h2, l2); split2(f3, h3, l3);
        *(__nv_bfloat162*)(oh_g + (size_t)r0 * DIM + col) = __nv_bfloat162(h0, h1);
        *(__nv_bfloat162*)(ol_g + (size_t)r0 * DIM + col) = __nv_bfloat162(l0, l1);
        *(__nv_bfloat162*)(oh_g + (size_t)r1 * DIM + col) = __nv_bfloat162(h2, h3);
        *(__nv_bfloat162*)(ol_g + (size_t)r1 * DIM + col) = __nv_bfloat162(l2, l3);
    }
}

// ---------------------------------------------------------------------------
// kernel_launch
// ---------------------------------------------------------------------------
extern "C" void kernel_launch(void* const* d_in, const int* in_sizes, int n_in,
                              void* d_out, int out_size)
{
    const float* hidden = (const float*)d_in[0];
    const float* cosb   = (const float*)d_in[1];
    const float* sinb   = (const float*)d_in[2];
    const float* qkv_w  = (const float*)d_in[3];
    const float* qkv_b  = (const float*)d_in[4];
    const float* proj_w = (const float*)d_in[5];
    const float* proj_b = (const float*)d_in[6];
    float* out = (float*)d_out;

    float* qkv;
    cudaGetSymbolAddress((void**)&qkv, g_qkv);

    __nv_bfloat16 *hid_h, *hid_l, *qw_h, *qw_l, *pw_h, *pw_l, *at_h, *at_l;
    __nv_bfloat16 *q_h, *q_l, *k_h, *k_l, *v_h, *v_l;
    cudaGetSymbolAddress((void**)&hid_h, g_hid_hi);
    cudaGetSymbolAddress((void**)&hid_l, g_hid_lo);
    cudaGetSymbolAddress((void**)&qw_h,  g_qkvw_hi);
    cudaGetSymbolAddress((void**)&qw_l,  g_qkvw_lo);
    cudaGetSymbolAddress((void**)&pw_h,  g_pw_hi);
    cudaGetSymbolAddress((void**)&pw_l,  g_pw_lo);
    cudaGetSymbolAddress((void**)&at_h,  g_att_hi);
    cudaGetSymbolAddress((void**)&at_l,  g_att_lo);
    cudaGetSymbolAddress((void**)&q_h,   g_q_hi);
    cudaGetSymbolAddress((void**)&q_l,   g_q_lo);
    cudaGetSymbolAddress((void**)&k_h,   g_k_hi);
    cudaGetSymbolAddress((void**)&k_l,   g_k_lo);
    cudaGetSymbolAddress((void**)&v_h,   g_v_hi);
    cudaGetSymbolAddress((void**)&v_l,   g_v_lo);

    cudaFuncSetAttribute(mma_gemm_bias,
                         cudaFuncAttributeMaxDynamicSharedMemorySize, GEMM_SMEM);
    cudaFuncSetAttribute(flash_mma_kernel,
                         cudaFuncAttributeMaxDynamicSharedMemorySize, ATTN_SMEM);

    // 0) split fp32 inputs into bf16 hi/lo
    {
        int n4 = SEQ * DIM / 4;
        split_bf16_kernel<<<(n4 + 255) / 256, 256>>>(hidden, hid_h, hid_l, n4);
        n4 = QKVN * DIM / 4;
        split_bf16_kernel<<<(n4 + 255) / 256, 256>>>(qkv_w, qw_h, qw_l, n4);
        n4 = DIM * DIM / 4;
        split_bf16_kernel<<<(n4 + 255) / 256, 256>>>(proj_w, pw_h, pw_l, n4);
    }

    // 1) QKV GEMM + bias (2-stage, 2 CTAs/SM, 1 barrier/chunk)
    mma_gemm_bias<<<dim3(QKVN / 128, SEQ / 128), 256, GEMM_SMEM>>>(
        hid_h, hid_l, qw_h, qw_l, qkv_b, qkv, SEQ, QKVN, DIM);

    // 2) RoPE + split + scatter to attention layouts
    rope_split_kernel<<<dim3(SEQ / 64, NH), 256>>>(
        qkv, cosb, sinb, q_h, q_l, k_h, k_l, v_h, v_l);

    // 3) Block-diagonal flash attention (2 CTAs/SM, 1 barrier/chunk)
    flash_mma_kernel<<<dim3(SEG / 128, 3, NH), 256, ATTN_SMEM>>>(
        q_h, q_l, k_h, k_l, v_h, v_l, at_h, at_l);

    // 4) Proj GEMM + bias
    mma_gemm_bias<<<dim3(DIM / 128, SEQ / 128), 256, GEMM_SMEM>>>(
        at_h, at_l, pw_h, pw_l, proj_b, out, SEQ, DIM, DIM);
}